// round 2
// baseline (speedup 1.0000x reference)
#include <cuda_runtime.h>

#define HW   16384      // 128*128
#define NCH  256        // h_fea channels
#define NB   8          // batch

typedef unsigned long long u64;

// ---------------- packed f32x2 helpers (sm_103a) ----------------
__device__ __forceinline__ u64 fma2(u64 a, u64 b, u64 c) {
    u64 d; asm("fma.rn.f32x2 %0,%1,%2,%3;" : "=l"(d) : "l"(a), "l"(b), "l"(c)); return d;
}
__device__ __forceinline__ u64 add2(u64 a, u64 b) {
    u64 d; asm("add.rn.f32x2 %0,%1,%2;" : "=l"(d) : "l"(a), "l"(b)); return d;
}
__device__ __forceinline__ u64 mul2(u64 a, u64 b) {
    u64 d; asm("mul.rn.f32x2 %0,%1,%2;" : "=l"(d) : "l"(a), "l"(b)); return d;
}
__device__ __forceinline__ u64 pk2(float x, float y) {
    u64 r; asm("mov.b64 %0,{%1,%2};" : "=l"(r) : "f"(x), "f"(y)); return r;
}
__device__ __forceinline__ void un2(u64 a, float& x, float& y) {
    asm("mov.b64 {%0,%1},%2;" : "=f"(x), "=f"(y) : "l"(a));
}
__device__ __forceinline__ u64 neg2(u64 a) { return a ^ 0x8000000080000000ULL; }
__device__ __forceinline__ u64 relu2(u64 a) {
    float x, y; un2(a, x, y);
    return pk2(fmaxf(x, 0.f), fmaxf(y, 0.f));
}
__device__ __forceinline__ float sig1(float x) {
    return __fdividef(1.f, 1.f + __expf(-x));
}
__device__ __forceinline__ u64 sig2(u64 a) {
    float x, y; un2(a, x, y);
    return pk2(sig1(x), sig1(y));
}

// ---------------- smem layout (all entries are duplicated f32x2 pairs) ----------------
// [0, 5632)     wmain: 256 rows x 22 (o<20: pdp_w1[o,c]; 20: decU_att[c]; 21: decL_att[c])
// [5632, 6032)  pdp tail: 20 outputs x 20 (i<10: *xh_u, i>=10: *xh_l)
// [6032, 6052)  decU tail (i<10: *xf, i>=10: *xh_u)
// [6052, 6072)  decL tail (i<10: *xf, i>=10: *xh_l)
#define SW 6072
#define O_W2    0
#define O_ATTW  200
#define O_ATTB  220
#define O_CUAW  222
#define O_CUAB  262
#define O_CUW   266
#define O_CLAW  466
#define O_CLAB  486
#define O_CLW   488
#define O_DUB   688
#define O_DUW   689
#define O_DLB   789
#define O_DLW   790
#define O_GUW   890
#define O_GUB   1090
#define O_CDUW  1100
#define O_GLW   1300
#define O_GLB   1500
#define O_CDLW  1510
#define SMEM_U64  (SW + 1710)
#define SMEM_BYTES (SMEM_U64 * 8)

// Output offsets (tuple flattened: xh_u_new, xh_l_new, att_u, att_l)
#define OUT_XHL  1310720
#define OUT_ATTU 2621440
#define OUT_ATTL 2752512

__global__ __launch_bounds__(128) void half_graph_kernel(
    const float* __restrict__ h_fea, const float* __restrict__ xh_u, const float* __restrict__ xh_l,
    const float* __restrict__ xf, const float* __restrict__ xp,
    const float* __restrict__ pdp_w1, const float* __restrict__ pdp_w2,
    const float* __restrict__ att_w, const float* __restrict__ att_b,
    const float* __restrict__ cU_aw, const float* __restrict__ cU_ab, const float* __restrict__ cU_w,
    const float* __restrict__ cL_aw, const float* __restrict__ cL_ab, const float* __restrict__ cL_w,
    const float* __restrict__ dU_aw, const float* __restrict__ dU_ab, const float* __restrict__ dU_w,
    const float* __restrict__ dL_aw, const float* __restrict__ dL_ab, const float* __restrict__ dL_w,
    const float* __restrict__ gU_w, const float* __restrict__ gU_b, const float* __restrict__ cdU_w,
    const float* __restrict__ gL_w, const float* __restrict__ gL_b, const float* __restrict__ cdL_w,
    float* __restrict__ out)
{
    extern __shared__ u64 sw[];
    const int tid = threadIdx.x;

    // ---- build duplicated weight tables in smem ----
    for (int idx = tid; idx < 256 * 22; idx += 128) {
        int c = idx / 22, o = idx - c * 22;
        float v = (o < 20) ? pdp_w1[o * 276 + c] : ((o == 20) ? dU_aw[c] : dL_aw[c]);
        sw[idx] = pk2(v, v);
    }
    for (int idx = tid; idx < 400; idx += 128) {
        int o = idx / 20, i = idx - o * 20;
        float v = pdp_w1[o * 276 + 256 + i];   // cat order [h_fea, xh_u, xh_l]
        sw[5632 + idx] = pk2(v, v);
    }
    if (tid < 20) {
        float v = dU_aw[256 + tid]; sw[6032 + tid] = pk2(v, v);   // [h_fea, xf, xh_u]
        float w = dL_aw[256 + tid]; sw[6052 + tid] = pk2(w, w);   // [h_fea, xf, xh_l]
    }
#define CPY(src, n_, off) for (int j = tid; j < (n_); j += 128) { float v = (src)[j]; sw[SW + (off) + j] = pk2(v, v); }
    CPY(pdp_w2, 200, O_W2)
    CPY(att_w, 20, O_ATTW)
    CPY(att_b, 2, O_ATTB)
    CPY(cU_aw, 40, O_CUAW)
    CPY(cU_ab, 4, O_CUAB)
    CPY(cU_w, 200, O_CUW)
    CPY(cL_aw, 20, O_CLAW)
    CPY(cL_ab, 2, O_CLAB)
    CPY(cL_w, 200, O_CLW)
    CPY(dU_ab, 1, O_DUB)
    CPY(dU_w, 100, O_DUW)
    CPY(dL_ab, 1, O_DLB)
    CPY(dL_w, 100, O_DLW)
    CPY(gU_w, 200, O_GUW)
    CPY(gU_b, 10, O_GUB)
    CPY(cdU_w, 200, O_CDUW)
    CPY(gL_w, 200, O_GLW)
    CPY(gL_b, 10, O_GLB)
    CPY(cdL_w, 200, O_CDLW)
#undef CPY
    __syncthreads();

    // ---- 2 pixels per thread (one f32x2 pair) ----
    const int P  = blockIdx.x * 256 + tid * 2;   // global pixel index
    const int n  = P >> 14;                      // blocks never straddle n
    const int pp = P & (HW - 1);

    const float* hb = h_fea + n * (NCH * HW) + pp;

    u64 acc[22];
#pragma unroll
    for (int o = 0; o < 22; o++) acc[o] = 0ull;

#pragma unroll 4
    for (int c = 0; c < NCH; c++) {
        float2 x = *reinterpret_cast<const float2*>(hb + c * HW);
        u64 xx = pk2(x.x, x.y);
        const ulonglong2* w = reinterpret_cast<const ulonglong2*>(&sw[c * 22]);
#pragma unroll
        for (int o = 0; o < 11; o++) {
            ulonglong2 wv = w[o];
            acc[2 * o]     = fma2(xx, wv.x, acc[2 * o]);
            acc[2 * o + 1] = fma2(xx, wv.y, acc[2 * o + 1]);
        }
    }

    // ---------------- tail / post (single pair, fully inlined) ----------------
    const int base10 = n * 10 * HW + pp;
    u64 xu[10], xl[10], xfv[10];
#pragma unroll
    for (int i = 0; i < 10; i++) {
        xu[i]  = *reinterpret_cast<const u64*>(xh_u + base10 + i * HW);
        xl[i]  = *reinterpret_cast<const u64*>(xh_l + base10 + i * HW);
        xfv[i] = *reinterpret_cast<const u64*>(xf   + base10 + i * HW);
    }

    // tails of the 276-channel dot products
#pragma unroll
    for (int o = 0; o < 20; o++) {
        u64 a = acc[o];
#pragma unroll
        for (int i = 0; i < 10; i++) {
            a = fma2(xu[i], sw[5632 + o * 20 + i], a);
            a = fma2(xl[i], sw[5632 + o * 20 + 10 + i], a);
        }
        acc[o] = a;
    }
    {
        u64 a = acc[20];
#pragma unroll
        for (int i = 0; i < 10; i++) {
            a = fma2(xfv[i], sw[6032 + i], a);
            a = fma2(xu[i],  sw[6042 + i], a);
        }
        acc[20] = a;
        u64 b = acc[21];
#pragma unroll
        for (int i = 0; i < 10; i++) {
            b = fma2(xfv[i], sw[6052 + i], b);
            b = fma2(xl[i],  sw[6062 + i], b);
        }
        acc[21] = b;
    }

    const u64 attu = sig2(add2(acc[20], sw[SW + O_DUB]));
    const u64 attl = sig2(add2(acc[21], sw[SW + O_DLB]));

    // t = relu(acc[0..19])
#pragma unroll
    for (int o = 0; o < 20; o++) acc[o] = relu2(acc[o]);

    // dp grouped 10x10
    u64 dpu[10], dpl[10];
#pragma unroll
    for (int j = 0; j < 10; j++) {
        u64 s = 0, s2 = 0;
#pragma unroll
        for (int i = 0; i < 10; i++) {
            s  = fma2(acc[i],      sw[SW + O_W2 + j * 10 + i], s);
            s2 = fma2(acc[10 + i], sw[SW + O_W2 + 100 + j * 10 + i], s2);
        }
        dpu[j] = relu2(s);
        dpl[j] = relu2(s2);
    }

    // grouped gate attention
    u64 au = sw[SW + O_ATTB + 0], al = sw[SW + O_ATTB + 1];
#pragma unroll
    for (int i = 0; i < 10; i++) {
        au = fma2(xu[i], sw[SW + O_ATTW + i], au);
        al = fma2(xl[i], sw[SW + O_ATTW + 10 + i], al);
    }
    au = sig2(au);
    al = sig2(al);

    u64 m[10];

    // =================== U branch ===================
    {
        u64 msg0 = 0, msg1 = 0, msg2 = 0, msg3 = 0, msg4 = 0,
            msg5 = 0, msg6 = 0, msg7 = 0, msg8 = 0, msg9 = 0;
#pragma unroll
        for (int p = 0; p < 4; p++) {
            u64 ca = sw[SW + O_CUAB + p];
            u64 pv[10];
#pragma unroll
            for (int i = 0; i < 10; i++) {
                pv[i] = *reinterpret_cast<const u64*>(xp + ((p * NB + n) * 10 + i) * HW + pp);
                ca = fma2(pv[i], sw[SW + O_CUAW + p * 10 + i], ca);
            }
            ca = sig2(ca);
            msg0 = fma2(pv[0], ca, msg0); msg1 = fma2(pv[1], ca, msg1);
            msg2 = fma2(pv[2], ca, msg2); msg3 = fma2(pv[3], ca, msg3);
            msg4 = fma2(pv[4], ca, msg4); msg5 = fma2(pv[5], ca, msg5);
            msg6 = fma2(pv[6], ca, msg6); msg7 = fma2(pv[7], ca, msg7);
            msg8 = fma2(pv[8], ca, msg8); msg9 = fma2(pv[9], ca, msg9);
        }
        u64 msg[10] = {msg0, msg1, msg2, msg3, msg4, msg5, msg6, msg7, msg8, msg9};
#pragma unroll
        for (int j = 0; j < 10; j++) {
            u64 s = 0;
#pragma unroll
            for (int i = 0; i < 10; i++) s = fma2(xu[i],  sw[SW + O_CUW + j * 20 + i], s);
#pragma unroll
            for (int i = 0; i < 10; i++) s = fma2(msg[i], sw[SW + O_CUW + j * 20 + 10 + i], s);
            u64 xph = relu2(s);
            u64 xlh = add2(mul2(dpl[j], al), mul2(xu[j], au));
            u64 s3 = 0;
#pragma unroll
            for (int i = 0; i < 10; i++) s3 = fma2(xfv[i], sw[SW + O_DUW + j * 10 + i], s3);
            u64 xfh = relu2(mul2(attu, s3));
            m[j] = add2(add2(xph, xlh), xfh);
        }
#pragma unroll
        for (int j = 0; j < 10; j++) {
            u64 g = sw[SW + O_GUB + j], cd = 0;
#pragma unroll
            for (int i = 0; i < 10; i++) {
                g  = fma2(xu[i], sw[SW + O_GUW + j * 20 + i], g);
                cd = fma2(xu[i], sw[SW + O_CDUW + j * 20 + i], cd);
            }
#pragma unroll
            for (int i = 0; i < 10; i++) {
                g  = fma2(m[i], sw[SW + O_GUW + j * 20 + 10 + i], g);
                cd = fma2(m[i], sw[SW + O_CDUW + j * 20 + 10 + i], cd);
            }
            g = sig2(g);
            cd = relu2(cd);
            u64 o = fma2(g, add2(cd, neg2(xu[j])), xu[j]);
            *reinterpret_cast<u64*>(out + (n * 10 + j) * HW + pp) = o;
        }
        *reinterpret_cast<u64*>(out + OUT_ATTU + n * HW + pp) = attu;
    }

    // =================== L branch ===================
    {
        u64 msg0 = 0, msg1 = 0, msg2 = 0, msg3 = 0, msg4 = 0,
            msg5 = 0, msg6 = 0, msg7 = 0, msg8 = 0, msg9 = 0;
#pragma unroll
        for (int p = 0; p < 2; p++) {
            u64 ca = sw[SW + O_CLAB + p];
            u64 pv[10];
#pragma unroll
            for (int i = 0; i < 10; i++) {
                pv[i] = *reinterpret_cast<const u64*>(xp + (((p + 4) * NB + n) * 10 + i) * HW + pp);
                ca = fma2(pv[i], sw[SW + O_CLAW + p * 10 + i], ca);
            }
            ca = sig2(ca);
            msg0 = fma2(pv[0], ca, msg0); msg1 = fma2(pv[1], ca, msg1);
            msg2 = fma2(pv[2], ca, msg2); msg3 = fma2(pv[3], ca, msg3);
            msg4 = fma2(pv[4], ca, msg4); msg5 = fma2(pv[5], ca, msg5);
            msg6 = fma2(pv[6], ca, msg6); msg7 = fma2(pv[7], ca, msg7);
            msg8 = fma2(pv[8], ca, msg8); msg9 = fma2(pv[9], ca, msg9);
        }
        u64 msg[10] = {msg0, msg1, msg2, msg3, msg4, msg5, msg6, msg7, msg8, msg9};
#pragma unroll
        for (int j = 0; j < 10; j++) {
            u64 s = 0;
#pragma unroll
            for (int i = 0; i < 10; i++) s = fma2(xl[i],  sw[SW + O_CLW + j * 20 + i], s);
#pragma unroll
            for (int i = 0; i < 10; i++) s = fma2(msg[i], sw[SW + O_CLW + j * 20 + 10 + i], s);
            u64 xph = relu2(s);
            u64 xuh = add2(mul2(dpu[j], au), mul2(xl[j], al));
            u64 s3 = 0;
#pragma unroll
            for (int i = 0; i < 10; i++) s3 = fma2(xfv[i], sw[SW + O_DLW + j * 10 + i], s3);
            u64 xfh = relu2(mul2(attl, s3));
            m[j] = add2(add2(xph, xuh), xfh);
        }
#pragma unroll
        for (int j = 0; j < 10; j++) {
            u64 g = sw[SW + O_GLB + j], cd = 0;
#pragma unroll
            for (int i = 0; i < 10; i++) {
                g  = fma2(xl[i], sw[SW + O_GLW + j * 20 + i], g);
                cd = fma2(xl[i], sw[SW + O_CDLW + j * 20 + i], cd);
            }
#pragma unroll
            for (int i = 0; i < 10; i++) {
                g  = fma2(m[i], sw[SW + O_GLW + j * 20 + 10 + i], g);
                cd = fma2(m[i], sw[SW + O_CDLW + j * 20 + 10 + i], cd);
            }
            g = sig2(g);
            cd = relu2(cd);
            u64 o = fma2(g, add2(cd, neg2(xl[j])), xl[j]);
            *reinterpret_cast<u64*>(out + OUT_XHL + (n * 10 + j) * HW + pp) = o;
        }
        *reinterpret_cast<u64*>(out + OUT_ATTL + n * HW + pp) = attl;
    }
}

extern "C" void kernel_launch(void* const* d_in, const int* in_sizes, int n_in,
                              void* d_out, int out_size)
{
    cudaFuncSetAttribute(half_graph_kernel,
                         cudaFuncAttributeMaxDynamicSharedMemorySize, SMEM_BYTES);
    half_graph_kernel<<<512, 128, SMEM_BYTES>>>(
        (const float*)d_in[0],  (const float*)d_in[1],  (const float*)d_in[2],
        (const float*)d_in[3],  (const float*)d_in[4],
        (const float*)d_in[5],  (const float*)d_in[6],
        (const float*)d_in[7],  (const float*)d_in[8],
        (const float*)d_in[9],  (const float*)d_in[10], (const float*)d_in[11],
        (const float*)d_in[12], (const float*)d_in[13], (const float*)d_in[14],
        (const float*)d_in[15], (const float*)d_in[16], (const float*)d_in[17],
        (const float*)d_in[18], (const float*)d_in[19], (const float*)d_in[20],
        (const float*)d_in[21], (const float*)d_in[22], (const float*)d_in[23],
        (const float*)d_in[24], (const float*)d_in[25], (const float*)d_in[26],
        (float*)d_out);
}

// round 3
// speedup vs baseline: 1.2861x; 1.2861x over previous
#include <cuda_runtime.h>

#define HW   16384      // 128*128
#define NCH  256
#define NB   8
#define PAIRS 65536     // 131072 pixels / 2

typedef unsigned long long u64;

// ---------------- packed f32x2 helpers (sm_103a) ----------------
__device__ __forceinline__ u64 fma2(u64 a, u64 b, u64 c) {
    u64 d; asm("fma.rn.f32x2 %0,%1,%2,%3;" : "=l"(d) : "l"(a), "l"(b), "l"(c)); return d;
}
__device__ __forceinline__ u64 add2(u64 a, u64 b) {
    u64 d; asm("add.rn.f32x2 %0,%1,%2;" : "=l"(d) : "l"(a), "l"(b)); return d;
}
__device__ __forceinline__ u64 mul2(u64 a, u64 b) {
    u64 d; asm("mul.rn.f32x2 %0,%1,%2;" : "=l"(d) : "l"(a), "l"(b)); return d;
}
__device__ __forceinline__ u64 pk2(float x, float y) {
    u64 r; asm("mov.b64 %0,{%1,%2};" : "=l"(r) : "f"(x), "f"(y)); return r;
}
__device__ __forceinline__ void un2(u64 a, float& x, float& y) {
    asm("mov.b64 {%0,%1},%2;" : "=f"(x), "=f"(y) : "l"(a));
}
__device__ __forceinline__ u64 neg2(u64 a) { return a ^ 0x8000000080000000ULL; }
__device__ __forceinline__ u64 relu2(u64 a) {
    float x, y; un2(a, x, y);
    return pk2(fmaxf(x, 0.f), fmaxf(y, 0.f));
}
__device__ __forceinline__ float sig1(float x) {
    return __fdividef(1.f, 1.f + __expf(-x));
}
__device__ __forceinline__ u64 sig2(u64 a) {
    float x, y; un2(a, x, y);
    return pk2(sig1(x), sig1(y));
}

// 22 partial dot products per pixel-pair, [o][pairIdx] layout
__device__ u64 g_scratch[22 * PAIRS];

// Output offsets (tuple flattened: xh_u_new, xh_l_new, att_u, att_l)
#define OUT_XHL  1310720
#define OUT_ATTU 2621440
#define OUT_ATTL 2752512

// =========================================================================
// Kernel 1: the [px x 256] @ [256 x 22] streaming GEMM over h_fea
// =========================================================================
__global__ __launch_bounds__(128) void k1_main(
    const float* __restrict__ h_fea,
    const float* __restrict__ pdp_w1,
    const float* __restrict__ dU_aw,
    const float* __restrict__ dL_aw)
{
    __shared__ u64 sw[256 * 22];            // 45056 B (static)
    const int tid = threadIdx.x;

    for (int idx = tid; idx < 256 * 22; idx += 128) {
        int c = idx / 22, o = idx - c * 22;
        float v = (o < 20) ? pdp_w1[o * 276 + c] : ((o == 20) ? dU_aw[c] : dL_aw[c]);
        sw[idx] = pk2(v, v);
    }
    __syncthreads();

    const int pair = blockIdx.x * 128 + tid;
    const int P  = pair * 2;
    const int n  = P >> 14;
    const int pp = P & (HW - 1);
    const float* hb = h_fea + n * (NCH * HW) + pp;

    u64 acc[22];
#pragma unroll
    for (int o = 0; o < 22; o++) acc[o] = 0ull;

#pragma unroll 8
    for (int c = 0; c < NCH; c++) {
        float2 x = *reinterpret_cast<const float2*>(hb + c * HW);
        u64 xx = pk2(x.x, x.y);
        const ulonglong2* w = reinterpret_cast<const ulonglong2*>(&sw[c * 22]);
#pragma unroll
        for (int o = 0; o < 11; o++) {
            ulonglong2 wv = w[o];
            acc[2 * o]     = fma2(xx, wv.x, acc[2 * o]);
            acc[2 * o + 1] = fma2(xx, wv.y, acc[2 * o + 1]);
        }
    }

#pragma unroll
    for (int o = 0; o < 22; o++)
        g_scratch[o * PAIRS + pair] = acc[o];
}

// =========================================================================
// Kernel 2: tails + graph logic
// =========================================================================
// smem layout (u64 duplicated pairs):
// [0,400)    pdp tail (20 outputs x 20: i<10 *xh_u, i>=10 *xh_l)
// [400,420)  decU tail (i<10 *xf, i>=10 *xh_u)
// [420,440)  decL tail (i<10 *xf, i>=10 *xh_l)
// [440,...)  small block
#define SB 440
#define O_W2    0
#define O_ATTW  200
#define O_ATTB  220
#define O_CUAW  222
#define O_CUAB  262
#define O_CUW   266
#define O_CLAW  466
#define O_CLAB  486
#define O_CLW   488
#define O_DUB   688
#define O_DUW   689
#define O_DLB   789
#define O_DLW   790
#define O_GUW   890
#define O_GUB   1090
#define O_CDUW  1100
#define O_GLW   1300
#define O_GLB   1500
#define O_CDLW  1510
#define SM2_U64 (SB + 1710)

__global__ __launch_bounds__(128) void k2_post(
    const float* __restrict__ xh_u, const float* __restrict__ xh_l,
    const float* __restrict__ xf, const float* __restrict__ xp,
    const float* __restrict__ pdp_w1, const float* __restrict__ pdp_w2,
    const float* __restrict__ att_w, const float* __restrict__ att_b,
    const float* __restrict__ cU_aw, const float* __restrict__ cU_ab, const float* __restrict__ cU_w,
    const float* __restrict__ cL_aw, const float* __restrict__ cL_ab, const float* __restrict__ cL_w,
    const float* __restrict__ dU_aw, const float* __restrict__ dU_ab, const float* __restrict__ dU_w,
    const float* __restrict__ dL_aw, const float* __restrict__ dL_ab, const float* __restrict__ dL_w,
    const float* __restrict__ gU_w, const float* __restrict__ gU_b, const float* __restrict__ cdU_w,
    const float* __restrict__ gL_w, const float* __restrict__ gL_b, const float* __restrict__ cdL_w,
    float* __restrict__ out)
{
    __shared__ u64 sw[SM2_U64];             // ~17 KB
    const int tid = threadIdx.x;

    for (int idx = tid; idx < 400; idx += 128) {
        int o = idx / 20, i = idx - o * 20;
        float v = pdp_w1[o * 276 + 256 + i];     // cat [h_fea, xh_u, xh_l]
        sw[idx] = pk2(v, v);
    }
    if (tid < 20) {
        float v = dU_aw[256 + tid]; sw[400 + tid] = pk2(v, v);   // [h_fea, xf, xh_u]
        float w = dL_aw[256 + tid]; sw[420 + tid] = pk2(w, w);   // [h_fea, xf, xh_l]
    }
#define CPY(src, n_, off) for (int j = tid; j < (n_); j += 128) { float v = (src)[j]; sw[SB + (off) + j] = pk2(v, v); }
    CPY(pdp_w2, 200, O_W2)
    CPY(att_w, 20, O_ATTW)
    CPY(att_b, 2, O_ATTB)
    CPY(cU_aw, 40, O_CUAW)
    CPY(cU_ab, 4, O_CUAB)
    CPY(cU_w, 200, O_CUW)
    CPY(cL_aw, 20, O_CLAW)
    CPY(cL_ab, 2, O_CLAB)
    CPY(cL_w, 200, O_CLW)
    CPY(dU_ab, 1, O_DUB)
    CPY(dU_w, 100, O_DUW)
    CPY(dL_ab, 1, O_DLB)
    CPY(dL_w, 100, O_DLW)
    CPY(gU_w, 200, O_GUW)
    CPY(gU_b, 10, O_GUB)
    CPY(cdU_w, 200, O_CDUW)
    CPY(gL_w, 200, O_GLW)
    CPY(gL_b, 10, O_GLB)
    CPY(cdL_w, 200, O_CDLW)
#undef CPY
    __syncthreads();

    const int pair = blockIdx.x * 128 + tid;
    const int P  = pair * 2;
    const int n  = P >> 14;
    const int pp = P & (HW - 1);

    u64 acc[22];
#pragma unroll
    for (int o = 0; o < 22; o++) acc[o] = g_scratch[o * PAIRS + pair];

    const int base10 = n * 10 * HW + pp;
    u64 xu[10], xl[10], xfv[10];
#pragma unroll
    for (int i = 0; i < 10; i++) {
        xu[i]  = *reinterpret_cast<const u64*>(xh_u + base10 + i * HW);
        xl[i]  = *reinterpret_cast<const u64*>(xh_l + base10 + i * HW);
        xfv[i] = *reinterpret_cast<const u64*>(xf   + base10 + i * HW);
    }

    // tails of the 276-channel dot products
#pragma unroll
    for (int o = 0; o < 20; o++) {
        u64 a = acc[o];
#pragma unroll
        for (int i = 0; i < 10; i++) {
            a = fma2(xu[i], sw[o * 20 + i], a);
            a = fma2(xl[i], sw[o * 20 + 10 + i], a);
        }
        acc[o] = a;
    }
    {
        u64 a = acc[20];
#pragma unroll
        for (int i = 0; i < 10; i++) {
            a = fma2(xfv[i], sw[400 + i], a);
            a = fma2(xu[i],  sw[410 + i], a);
        }
        acc[20] = a;
        u64 b = acc[21];
#pragma unroll
        for (int i = 0; i < 10; i++) {
            b = fma2(xfv[i], sw[420 + i], b);
            b = fma2(xl[i],  sw[430 + i], b);
        }
        acc[21] = b;
    }

    const u64 attu = sig2(add2(acc[20], sw[SB + O_DUB]));
    const u64 attl = sig2(add2(acc[21], sw[SB + O_DLB]));

#pragma unroll
    for (int o = 0; o < 20; o++) acc[o] = relu2(acc[o]);

    // dp grouped 10x10
    u64 dpu[10], dpl[10];
#pragma unroll
    for (int j = 0; j < 10; j++) {
        u64 s = 0, s2 = 0;
#pragma unroll
        for (int i = 0; i < 10; i++) {
            s  = fma2(acc[i],      sw[SB + O_W2 + j * 10 + i], s);
            s2 = fma2(acc[10 + i], sw[SB + O_W2 + 100 + j * 10 + i], s2);
        }
        dpu[j] = relu2(s);
        dpl[j] = relu2(s2);
    }

    // grouped gate attention
    u64 au = sw[SB + O_ATTB + 0], al = sw[SB + O_ATTB + 1];
#pragma unroll
    for (int i = 0; i < 10; i++) {
        au = fma2(xu[i], sw[SB + O_ATTW + i], au);
        al = fma2(xl[i], sw[SB + O_ATTW + 10 + i], al);
    }
    au = sig2(au);
    al = sig2(al);

    u64 m[10];

    // =================== U branch ===================
    {
        u64 msg0 = 0, msg1 = 0, msg2 = 0, msg3 = 0, msg4 = 0,
            msg5 = 0, msg6 = 0, msg7 = 0, msg8 = 0, msg9 = 0;
#pragma unroll
        for (int p = 0; p < 4; p++) {
            u64 ca = sw[SB + O_CUAB + p];
            u64 pv[10];
#pragma unroll
            for (int i = 0; i < 10; i++) {
                pv[i] = *reinterpret_cast<const u64*>(xp + ((p * NB + n) * 10 + i) * HW + pp);
                ca = fma2(pv[i], sw[SB + O_CUAW + p * 10 + i], ca);
            }
            ca = sig2(ca);
            msg0 = fma2(pv[0], ca, msg0); msg1 = fma2(pv[1], ca, msg1);
            msg2 = fma2(pv[2], ca, msg2); msg3 = fma2(pv[3], ca, msg3);
            msg4 = fma2(pv[4], ca, msg4); msg5 = fma2(pv[5], ca, msg5);
            msg6 = fma2(pv[6], ca, msg6); msg7 = fma2(pv[7], ca, msg7);
            msg8 = fma2(pv[8], ca, msg8); msg9 = fma2(pv[9], ca, msg9);
        }
        u64 msg[10] = {msg0, msg1, msg2, msg3, msg4, msg5, msg6, msg7, msg8, msg9};
#pragma unroll
        for (int j = 0; j < 10; j++) {
            u64 s = 0;
#pragma unroll
            for (int i = 0; i < 10; i++) s = fma2(xu[i],  sw[SB + O_CUW + j * 20 + i], s);
#pragma unroll
            for (int i = 0; i < 10; i++) s = fma2(msg[i], sw[SB + O_CUW + j * 20 + 10 + i], s);
            u64 xph = relu2(s);
            u64 xlh = add2(mul2(dpl[j], al), mul2(xu[j], au));
            u64 s3 = 0;
#pragma unroll
            for (int i = 0; i < 10; i++) s3 = fma2(xfv[i], sw[SB + O_DUW + j * 10 + i], s3);
            u64 xfh = relu2(mul2(attu, s3));
            m[j] = add2(add2(xph, xlh), xfh);
        }
#pragma unroll
        for (int j = 0; j < 10; j++) {
            u64 g = sw[SB + O_GUB + j], cd = 0;
#pragma unroll
            for (int i = 0; i < 10; i++) {
                g  = fma2(xu[i], sw[SB + O_GUW + j * 20 + i], g);
                cd = fma2(xu[i], sw[SB + O_CDUW + j * 20 + i], cd);
            }
#pragma unroll
            for (int i = 0; i < 10; i++) {
                g  = fma2(m[i], sw[SB + O_GUW + j * 20 + 10 + i], g);
                cd = fma2(m[i], sw[SB + O_CDUW + j * 20 + 10 + i], cd);
            }
            g = sig2(g);
            cd = relu2(cd);
            u64 o = fma2(g, add2(cd, neg2(xu[j])), xu[j]);
            *reinterpret_cast<u64*>(out + (n * 10 + j) * HW + pp) = o;
        }
        *reinterpret_cast<u64*>(out + OUT_ATTU + n * HW + pp) = attu;
    }

    // =================== L branch ===================
    {
        u64 msg0 = 0, msg1 = 0, msg2 = 0, msg3 = 0, msg4 = 0,
            msg5 = 0, msg6 = 0, msg7 = 0, msg8 = 0, msg9 = 0;
#pragma unroll
        for (int p = 0; p < 2; p++) {
            u64 ca = sw[SB + O_CLAB + p];
            u64 pv[10];
#pragma unroll
            for (int i = 0; i < 10; i++) {
                pv[i] = *reinterpret_cast<const u64*>(xp + (((p + 4) * NB + n) * 10 + i) * HW + pp);
                ca = fma2(pv[i], sw[SB + O_CLAW + p * 10 + i], ca);
            }
            ca = sig2(ca);
            msg0 = fma2(pv[0], ca, msg0); msg1 = fma2(pv[1], ca, msg1);
            msg2 = fma2(pv[2], ca, msg2); msg3 = fma2(pv[3], ca, msg3);
            msg4 = fma2(pv[4], ca, msg4); msg5 = fma2(pv[5], ca, msg5);
            msg6 = fma2(pv[6], ca, msg6); msg7 = fma2(pv[7], ca, msg7);
            msg8 = fma2(pv[8], ca, msg8); msg9 = fma2(pv[9], ca, msg9);
        }
        u64 msg[10] = {msg0, msg1, msg2, msg3, msg4, msg5, msg6, msg7, msg8, msg9};
#pragma unroll
        for (int j = 0; j < 10; j++) {
            u64 s = 0;
#pragma unroll
            for (int i = 0; i < 10; i++) s = fma2(xl[i],  sw[SB + O_CLW + j * 20 + i], s);
#pragma unroll
            for (int i = 0; i < 10; i++) s = fma2(msg[i], sw[SB + O_CLW + j * 20 + 10 + i], s);
            u64 xph = relu2(s);
            u64 xuh = add2(mul2(dpu[j], au), mul2(xl[j], al));
            u64 s3 = 0;
#pragma unroll
            for (int i = 0; i < 10; i++) s3 = fma2(xfv[i], sw[SB + O_DLW + j * 10 + i], s3);
            u64 xfh = relu2(mul2(attl, s3));
            m[j] = add2(add2(xph, xuh), xfh);
        }
#pragma unroll
        for (int j = 0; j < 10; j++) {
            u64 g = sw[SB + O_GLB + j], cd = 0;
#pragma unroll
            for (int i = 0; i < 10; i++) {
                g  = fma2(xl[i], sw[SB + O_GLW + j * 20 + i], g);
                cd = fma2(xl[i], sw[SB + O_CDLW + j * 20 + i], cd);
            }
#pragma unroll
            for (int i = 0; i < 10; i++) {
                g  = fma2(m[i], sw[SB + O_GLW + j * 20 + 10 + i], g);
                cd = fma2(m[i], sw[SB + O_CDLW + j * 20 + 10 + i], cd);
            }
            g = sig2(g);
            cd = relu2(cd);
            u64 o = fma2(g, add2(cd, neg2(xl[j])), xl[j]);
            *reinterpret_cast<u64*>(out + OUT_XHL + (n * 10 + j) * HW + pp) = o;
        }
        *reinterpret_cast<u64*>(out + OUT_ATTL + n * HW + pp) = attl;
    }
}

extern "C" void kernel_launch(void* const* d_in, const int* in_sizes, int n_in,
                              void* d_out, int out_size)
{
    k1_main<<<512, 128>>>(
        (const float*)d_in[0],   // h_fea
        (const float*)d_in[5],   // pdp_w1
        (const float*)d_in[15],  // decU_att_w
        (const float*)d_in[18]); // decL_att_w

    k2_post<<<512, 128>>>(
        (const float*)d_in[1],  (const float*)d_in[2],
        (const float*)d_in[3],  (const float*)d_in[4],
        (const float*)d_in[5],  (const float*)d_in[6],
        (const float*)d_in[7],  (const float*)d_in[8],
        (const float*)d_in[9],  (const float*)d_in[10], (const float*)d_in[11],
        (const float*)d_in[12], (const float*)d_in[13], (const float*)d_in[14],
        (const float*)d_in[15], (const float*)d_in[16], (const float*)d_in[17],
        (const float*)d_in[18], (const float*)d_in[19], (const float*)d_in[20],
        (const float*)d_in[21], (const float*)d_in[22], (const float*)d_in[23],
        (const float*)d_in[24], (const float*)d_in[25], (const float*)d_in[26],
        (float*)d_out);
}

// round 4
// speedup vs baseline: 1.3498x; 1.0495x over previous
#include <cuda_runtime.h>

#define HW   16384      // 128*128
#define NCH  256
#define NB   8
#define PAIRS 65536     // 131072 pixels / 2
#define NPIX 131072

typedef unsigned long long u64;

// ---------------- packed f32x2 helpers (sm_103a) ----------------
__device__ __forceinline__ u64 fma2(u64 a, u64 b, u64 c) {
    u64 d; asm("fma.rn.f32x2 %0,%1,%2,%3;" : "=l"(d) : "l"(a), "l"(b), "l"(c)); return d;
}
__device__ __forceinline__ u64 pk2(float x, float y) {
    u64 r; asm("mov.b64 %0,{%1,%2};" : "=l"(r) : "f"(x), "f"(y)); return r;
}
__device__ __forceinline__ float sig1(float x) {
    return __fdividef(1.f, 1.f + __expf(-x));
}

// 22 partial dot products per pixel-pair, [o][pairIdx] layout (u64 = 2 px)
__device__ u64 g_scratch[22 * PAIRS];

// Output offsets (tuple flattened: xh_u_new, xh_l_new, att_u, att_l)
#define OUT_XHL  1310720
#define OUT_ATTU 2621440
#define OUT_ATTL 2752512

// =========================================================================
// Kernel 1: [px x 256] @ [256 x 22] streaming GEMM over h_fea,
// software-pipelined register double-buffer (sustained MLP = 8).
// =========================================================================
__global__ __launch_bounds__(128, 4) void k1_main(
    const float* __restrict__ h_fea,
    const float* __restrict__ pdp_w1,
    const float* __restrict__ dU_aw,
    const float* __restrict__ dL_aw)
{
    __shared__ u64 swk[256 * 22];           // 45056 B
    const int tid = threadIdx.x;

    for (int idx = tid; idx < 256 * 22; idx += 128) {
        int c = idx / 22, o = idx - c * 22;
        float v = (o < 20) ? pdp_w1[o * 276 + c] : ((o == 20) ? dU_aw[c] : dL_aw[c]);
        swk[idx] = pk2(v, v);
    }
    __syncthreads();

    const int pair = blockIdx.x * 128 + tid;
    const int P  = pair * 2;
    const int n  = P >> 14;
    const int pp = P & (HW - 1);
    const float* hb = h_fea + n * (NCH * HW) + pp;

    u64 acc[22];
#pragma unroll
    for (int o = 0; o < 22; o++) acc[o] = 0ull;

    u64 bA[8], bB[8];

#define LOAD_CHUNK(B, C0)                                                     \
    _Pragma("unroll")                                                         \
    for (int j = 0; j < 8; j++)                                               \
        B[j] = *reinterpret_cast<const u64*>(hb + ((C0) + j) * HW);

#define COMP_CHUNK(B, C0)                                                     \
    _Pragma("unroll")                                                         \
    for (int j = 0; j < 8; j++) {                                             \
        u64 xx = B[j];                                                        \
        const ulonglong2* w =                                                 \
            reinterpret_cast<const ulonglong2*>(&swk[((C0) + j) * 22]);       \
        _Pragma("unroll")                                                     \
        for (int o = 0; o < 11; o++) {                                        \
            ulonglong2 wv = w[o];                                             \
            acc[2 * o]     = fma2(xx, wv.x, acc[2 * o]);                      \
            acc[2 * o + 1] = fma2(xx, wv.y, acc[2 * o + 1]);                  \
        }                                                                     \
    }

    LOAD_CHUNK(bA, 0)
#pragma unroll 1
    for (int c0 = 0; c0 < 256; c0 += 16) {
        LOAD_CHUNK(bB, c0 + 8)
        COMP_CHUNK(bA, c0)
        const int nxt = (c0 + 16) & 255;      // last iter reloads chunk 0 (dead)
        LOAD_CHUNK(bA, nxt)
        COMP_CHUNK(bB, c0 + 8)
    }
#undef LOAD_CHUNK
#undef COMP_CHUNK

#pragma unroll
    for (int o = 0; o < 22; o++)
        g_scratch[o * PAIRS + pair] = acc[o];
}

// =========================================================================
// Kernel 2: tails + graph logic — SCALAR, 1 pixel/thread.
// =========================================================================
// smem f32 layout:
// [0,400)    pdp tail (20 outputs x 20: i<10 *xh_u, i>=10 *xh_l)
// [400,420)  decU tail (i<10 *xf, i>=10 *xh_u)
// [420,440)  decL tail (i<10 *xf, i>=10 *xh_l)
// [440,...)  small block
#define SB 440
#define O_W2    0
#define O_ATTW  200
#define O_ATTB  220
#define O_CUAW  222
#define O_CUAB  262
#define O_CUW   266
#define O_CLAW  466
#define O_CLAB  486
#define O_CLW   488
#define O_DUB   688
#define O_DUW   689
#define O_DLB   789
#define O_DLW   790
#define O_GUW   890
#define O_GUB   1090
#define O_CDUW  1100
#define O_GLW   1300
#define O_GLB   1500
#define O_CDLW  1510
#define SM2_F32 (SB + 1710)

__global__ __launch_bounds__(128, 4) void k2_post(
    const float* __restrict__ xh_u, const float* __restrict__ xh_l,
    const float* __restrict__ xf, const float* __restrict__ xp,
    const float* __restrict__ pdp_w1, const float* __restrict__ pdp_w2,
    const float* __restrict__ att_w, const float* __restrict__ att_b,
    const float* __restrict__ cU_aw, const float* __restrict__ cU_ab, const float* __restrict__ cU_w,
    const float* __restrict__ cL_aw, const float* __restrict__ cL_ab, const float* __restrict__ cL_w,
    const float* __restrict__ dU_aw, const float* __restrict__ dU_ab, const float* __restrict__ dU_w,
    const float* __restrict__ dL_aw, const float* __restrict__ dL_ab, const float* __restrict__ dL_w,
    const float* __restrict__ gU_w, const float* __restrict__ gU_b, const float* __restrict__ cdU_w,
    const float* __restrict__ gL_w, const float* __restrict__ gL_b, const float* __restrict__ cdL_w,
    float* __restrict__ out)
{
    __shared__ float sw[SM2_F32];           // 8.6 KB
    const int tid = threadIdx.x;

    for (int idx = tid; idx < 400; idx += 128) {
        int o = idx / 20, i = idx - o * 20;
        sw[idx] = pdp_w1[o * 276 + 256 + i];      // cat [h_fea, xh_u, xh_l]
    }
    if (tid < 20) {
        sw[400 + tid] = dU_aw[256 + tid];         // [h_fea, xf, xh_u]
        sw[420 + tid] = dL_aw[256 + tid];         // [h_fea, xf, xh_l]
    }
#define CPY(src, n_, off) for (int j = tid; j < (n_); j += 128) sw[SB + (off) + j] = (src)[j];
    CPY(pdp_w2, 200, O_W2)
    CPY(att_w, 20, O_ATTW)
    CPY(att_b, 2, O_ATTB)
    CPY(cU_aw, 40, O_CUAW)
    CPY(cU_ab, 4, O_CUAB)
    CPY(cU_w, 200, O_CUW)
    CPY(cL_aw, 20, O_CLAW)
    CPY(cL_ab, 2, O_CLAB)
    CPY(cL_w, 200, O_CLW)
    CPY(dU_ab, 1, O_DUB)
    CPY(dU_w, 100, O_DUW)
    CPY(dL_ab, 1, O_DLB)
    CPY(dL_w, 100, O_DLW)
    CPY(gU_w, 200, O_GUW)
    CPY(gU_b, 10, O_GUB)
    CPY(cdU_w, 200, O_CDUW)
    CPY(gL_w, 200, O_GLW)
    CPY(gL_b, 10, O_GLB)
    CPY(cdL_w, 200, O_CDLW)
#undef CPY
    __syncthreads();

    const int P  = blockIdx.x * 128 + tid;  // one pixel per thread
    const int n  = P >> 14;
    const int pp = P & (HW - 1);

    // scratch view as scalar floats: f[o * NPIX + P]
    const float* gsf = reinterpret_cast<const float*>(g_scratch);

    float acc[22];
#pragma unroll
    for (int o = 0; o < 22; o++) acc[o] = gsf[o * NPIX + P];

    const int base10 = n * 10 * HW + pp;
    float xu[10], xl[10], xfv[10];
#pragma unroll
    for (int i = 0; i < 10; i++) {
        xu[i]  = xh_u[base10 + i * HW];
        xl[i]  = xh_l[base10 + i * HW];
        xfv[i] = xf[base10 + i * HW];
    }

    // tails of the 276-channel dot products
#pragma unroll
    for (int o = 0; o < 20; o++) {
        float a = acc[o];
#pragma unroll
        for (int i = 0; i < 10; i++) {
            a = fmaf(xu[i], sw[o * 20 + i], a);
            a = fmaf(xl[i], sw[o * 20 + 10 + i], a);
        }
        acc[o] = a;
    }
    {
        float a = acc[20];
#pragma unroll
        for (int i = 0; i < 10; i++) {
            a = fmaf(xfv[i], sw[400 + i], a);
            a = fmaf(xu[i],  sw[410 + i], a);
        }
        acc[20] = a;
        float b = acc[21];
#pragma unroll
        for (int i = 0; i < 10; i++) {
            b = fmaf(xfv[i], sw[420 + i], b);
            b = fmaf(xl[i],  sw[430 + i], b);
        }
        acc[21] = b;
    }

    const float attu = sig1(acc[20] + sw[SB + O_DUB]);
    const float attl = sig1(acc[21] + sw[SB + O_DLB]);

#pragma unroll
    for (int o = 0; o < 20; o++) acc[o] = fmaxf(acc[o], 0.f);

    // dp grouped 10x10
    float dpu[10], dpl[10];
#pragma unroll
    for (int j = 0; j < 10; j++) {
        float s = 0.f, s2 = 0.f;
#pragma unroll
        for (int i = 0; i < 10; i++) {
            s  = fmaf(acc[i],      sw[SB + O_W2 + j * 10 + i], s);
            s2 = fmaf(acc[10 + i], sw[SB + O_W2 + 100 + j * 10 + i], s2);
        }
        dpu[j] = fmaxf(s, 0.f);
        dpl[j] = fmaxf(s2, 0.f);
    }

    // grouped gate attention
    float au = sw[SB + O_ATTB + 0], al = sw[SB + O_ATTB + 1];
#pragma unroll
    for (int i = 0; i < 10; i++) {
        au = fmaf(xu[i], sw[SB + O_ATTW + i], au);
        al = fmaf(xl[i], sw[SB + O_ATTW + 10 + i], al);
    }
    au = sig1(au);
    al = sig1(al);

    float m[10];

    // =================== U branch ===================
    {
        float msg0 = 0.f, msg1 = 0.f, msg2 = 0.f, msg3 = 0.f, msg4 = 0.f,
              msg5 = 0.f, msg6 = 0.f, msg7 = 0.f, msg8 = 0.f, msg9 = 0.f;
#pragma unroll
        for (int p = 0; p < 4; p++) {
            float ca = sw[SB + O_CUAB + p];
            float pv[10];
#pragma unroll
            for (int i = 0; i < 10; i++) {
                pv[i] = xp[((p * NB + n) * 10 + i) * HW + pp];
                ca = fmaf(pv[i], sw[SB + O_CUAW + p * 10 + i], ca);
            }
            ca = sig1(ca);
            msg0 = fmaf(pv[0], ca, msg0); msg1 = fmaf(pv[1], ca, msg1);
            msg2 = fmaf(pv[2], ca, msg2); msg3 = fmaf(pv[3], ca, msg3);
            msg4 = fmaf(pv[4], ca, msg4); msg5 = fmaf(pv[5], ca, msg5);
            msg6 = fmaf(pv[6], ca, msg6); msg7 = fmaf(pv[7], ca, msg7);
            msg8 = fmaf(pv[8], ca, msg8); msg9 = fmaf(pv[9], ca, msg9);
        }
        float msg[10] = {msg0, msg1, msg2, msg3, msg4, msg5, msg6, msg7, msg8, msg9};
#pragma unroll
        for (int j = 0; j < 10; j++) {
            float s = 0.f;
#pragma unroll
            for (int i = 0; i < 10; i++) s = fmaf(xu[i],  sw[SB + O_CUW + j * 20 + i], s);
#pragma unroll
            for (int i = 0; i < 10; i++) s = fmaf(msg[i], sw[SB + O_CUW + j * 20 + 10 + i], s);
            float xph = fmaxf(s, 0.f);
            float xlh = dpl[j] * al + xu[j] * au;
            float s3 = 0.f;
#pragma unroll
            for (int i = 0; i < 10; i++) s3 = fmaf(xfv[i], sw[SB + O_DUW + j * 10 + i], s3);
            float xfh = fmaxf(attu * s3, 0.f);
            m[j] = xph + xlh + xfh;
        }
#pragma unroll
        for (int j = 0; j < 10; j++) {
            float g = sw[SB + O_GUB + j], cd = 0.f;
#pragma unroll
            for (int i = 0; i < 10; i++) {
                g  = fmaf(xu[i], sw[SB + O_GUW + j * 20 + i], g);
                cd = fmaf(xu[i], sw[SB + O_CDUW + j * 20 + i], cd);
            }
#pragma unroll
            for (int i = 0; i < 10; i++) {
                g  = fmaf(m[i], sw[SB + O_GUW + j * 20 + 10 + i], g);
                cd = fmaf(m[i], sw[SB + O_CDUW + j * 20 + 10 + i], cd);
            }
            g = sig1(g);
            cd = fmaxf(cd, 0.f);
            out[(n * 10 + j) * HW + pp] = fmaf(g, cd - xu[j], xu[j]);
        }
        out[OUT_ATTU + n * HW + pp] = attu;
    }

    // =================== L branch ===================
    {
        float msg0 = 0.f, msg1 = 0.f, msg2 = 0.f, msg3 = 0.f, msg4 = 0.f,
              msg5 = 0.f, msg6 = 0.f, msg7 = 0.f, msg8 = 0.f, msg9 = 0.f;
#pragma unroll
        for (int p = 0; p < 2; p++) {
            float ca = sw[SB + O_CLAB + p];
            float pv[10];
#pragma unroll
            for (int i = 0; i < 10; i++) {
                pv[i] = xp[(((p + 4) * NB + n) * 10 + i) * HW + pp];
                ca = fmaf(pv[i], sw[SB + O_CLAW + p * 10 + i], ca);
            }
            ca = sig1(ca);
            msg0 = fmaf(pv[0], ca, msg0); msg1 = fmaf(pv[1], ca, msg1);
            msg2 = fmaf(pv[2], ca, msg2); msg3 = fmaf(pv[3], ca, msg3);
            msg4 = fmaf(pv[4], ca, msg4); msg5 = fmaf(pv[5], ca, msg5);
            msg6 = fmaf(pv[6], ca, msg6); msg7 = fmaf(pv[7], ca, msg7);
            msg8 = fmaf(pv[8], ca, msg8); msg9 = fmaf(pv[9], ca, msg9);
        }
        float msg[10] = {msg0, msg1, msg2, msg3, msg4, msg5, msg6, msg7, msg8, msg9};
#pragma unroll
        for (int j = 0; j < 10; j++) {
            float s = 0.f;
#pragma unroll
            for (int i = 0; i < 10; i++) s = fmaf(xl[i],  sw[SB + O_CLW + j * 20 + i], s);
#pragma unroll
            for (int i = 0; i < 10; i++) s = fmaf(msg[i], sw[SB + O_CLW + j * 20 + 10 + i], s);
            float xph = fmaxf(s, 0.f);
            float xuh = dpu[j] * au + xl[j] * al;
            float s3 = 0.f;
#pragma unroll
            for (int i = 0; i < 10; i++) s3 = fmaf(xfv[i], sw[SB + O_DLW + j * 10 + i], s3);
            float xfh = fmaxf(attl * s3, 0.f);
            m[j] = xph + xuh + xfh;
        }
#pragma unroll
        for (int j = 0; j < 10; j++) {
            float g = sw[SB + O_GLB + j], cd = 0.f;
#pragma unroll
            for (int i = 0; i < 10; i++) {
                g  = fmaf(xl[i], sw[SB + O_GLW + j * 20 + i], g);
                cd = fmaf(xl[i], sw[SB + O_CDLW + j * 20 + i], cd);
            }
#pragma unroll
            for (int i = 0; i < 10; i++) {
                g  = fmaf(m[i], sw[SB + O_GLW + j * 20 + 10 + i], g);
                cd = fmaf(m[i], sw[SB + O_CDLW + j * 20 + 10 + i], cd);
            }
            g = sig1(g);
            cd = fmaxf(cd, 0.f);
            out[OUT_XHL + (n * 10 + j) * HW + pp] = fmaf(g, cd - xl[j], xl[j]);
        }
        out[OUT_ATTL + n * HW + pp] = attl;
    }
}

extern "C" void kernel_launch(void* const* d_in, const int* in_sizes, int n_in,
                              void* d_out, int out_size)
{
    k1_main<<<512, 128>>>(
        (const float*)d_in[0],   // h_fea
        (const float*)d_in[5],   // pdp_w1
        (const float*)d_in[15],  // decU_att_w
        (const float*)d_in[18]); // decL_att_w

    k2_post<<<1024, 128>>>(
        (const float*)d_in[1],  (const float*)d_in[2],
        (const float*)d_in[3],  (const float*)d_in[4],
        (const float*)d_in[5],  (const float*)d_in[6],
        (const float*)d_in[7],  (const float*)d_in[8],
        (const float*)d_in[9],  (const float*)d_in[10], (const float*)d_in[11],
        (const float*)d_in[12], (const float*)d_in[13], (const float*)d_in[14],
        (const float*)d_in[15], (const float*)d_in[16], (const float*)d_in[17],
        (const float*)d_in[18], (const float*)d_in[19], (const float*)d_in[20],
        (const float*)d_in[21], (const float*)d_in[22], (const float*)d_in[23],
        (const float*)d_in[24], (const float*)d_in[25], (const float*)d_in[26],
        (float*)d_out);
}